// round 8
// baseline (speedup 1.0000x reference)
#include <cuda_runtime.h>
#include <cuda_bf16.h>
#include <mma.h>
#include <math.h>
#include <cstdint>

using namespace nvcuda;

#define BSZ 8
#define TD  64
#define TE  512
#define HH  512

// fp32 scratch
__device__ float g_u [BSZ*TD*HH];
__device__ float g_v [BSZ*TE*HH];
__device__ float g_S1[BSZ*HH];
__device__ float g_S2[BSZ*HH];
__device__ float g_pA[2*BSZ*TD*TE];          // split-K raw partials (reused)

// bf16 hi/lo scratch
__device__ __nv_bfloat16 g_Wh [HH*2*HH],  g_Wl [HH*2*HH];
__device__ __nv_bfloat16 g_Dh [BSZ*TD*HH], g_Dl [BSZ*TD*HH];   // dec
__device__ __nv_bfloat16 g_Enh[BSZ*TE*HH], g_Enl[BSZ*TE*HH];   // enc
__device__ __nv_bfloat16 g_ETh[BSZ*HH*TE], g_ETl[BSZ*HH*TE];   // enc transposed [b,d,j]
__device__ __nv_bfloat16 g_Euh[BSZ*TD*HH], g_Eul[BSZ*TD*HH];
__device__ __nv_bfloat16 g_Evh[BSZ*TE*HH], g_Evl[BSZ*TE*HH];
__device__ __nv_bfloat16 g_Lh [BSZ*TD*TE], g_Ll [BSZ*TD*TE];   // lse hi/lo

__device__ __forceinline__ void cvt2(float x, __nv_bfloat16& h, __nv_bfloat16& l) {
    h = __float2bfloat16(x);
    l = __float2bfloat16(x - __bfloat162float(h));
}

__device__ __forceinline__ unsigned int s2u(const void* p) {
    return (unsigned int)__cvta_generic_to_shared(p);
}
__device__ __forceinline__ void cpa16(unsigned int d, const void* s) {
    asm volatile("cp.async.cg.shared.global [%0], [%1], 16;\n" :: "r"(d), "l"(s));
}
#define CP_COMMIT() asm volatile("cp.async.commit_group;\n" ::: "memory")
#define CP_WAIT0()  asm volatile("cp.async.wait_group 0;\n" ::: "memory")
#define CP_WAIT1()  asm volatile("cp.async.wait_group 1;\n" ::: "memory")

// ---------------------------------------------------------------------------
// Convert W, dec, enc to hi/lo bf16 (flat, one pass).
// ---------------------------------------------------------------------------
#define N_W   (HH*2*HH)          // 524288
#define N_D   (BSZ*TD*HH)        // 262144
#define N_E   (BSZ*TE*HH)        // 2097152
__global__ void __launch_bounds__(256) cvt_all(
    const float* __restrict__ W, const float* __restrict__ dec,
    const float* __restrict__ enc)
{
    long i = ((long)blockIdx.x * 256 + threadIdx.x) * 4;
    const float* src; __nv_bfloat16 *H, *L;
    if (i < N_W)            { src = W   + i;              H = g_Wh  + i;              L = g_Wl  + i; }
    else if (i < N_W + N_D) { long o = i - N_W;   src = dec + o; H = g_Dh + o;  L = g_Dl + o; }
    else                    { long o = i - N_W - N_D; src = enc + o; H = g_Enh + o; L = g_Enl + o; }
    float4 x = *reinterpret_cast<const float4*>(src);
    __nv_bfloat16 h0,h1,h2,h3,l0,l1,l2,l3;
    cvt2(x.x,h0,l0); cvt2(x.y,h1,l1); cvt2(x.z,h2,l2); cvt2(x.w,h3,l3);
    reinterpret_cast<__nv_bfloat162*>(H)[0] = __nv_bfloat162(h0,h1);
    reinterpret_cast<__nv_bfloat162*>(H)[1] = __nv_bfloat162(h2,h3);
    reinterpret_cast<__nv_bfloat162*>(L)[0] = __nv_bfloat162(l0,l1);
    reinterpret_cast<__nv_bfloat162*>(L)[1] = __nv_bfloat162(l2,l3);
}

// enc [b,j,d] -> encT hi/lo [b,d,j]
__global__ void encT_k(const float* __restrict__ enc)
{
    __shared__ float t[32][33];
    const int b = blockIdx.z;
    const int j0 = blockIdx.y * 32, d0 = blockIdx.x * 32;
    const float* e = enc + (long)b * TE * HH;
    #pragma unroll
    for (int p = 0; p < 4; ++p)
        t[threadIdx.y + p*8][threadIdx.x] =
            e[(long)(j0 + threadIdx.y + p*8) * HH + d0 + threadIdx.x];
    __syncthreads();
    #pragma unroll
    for (int p = 0; p < 4; ++p) {
        int d = d0 + threadIdx.y + p*8;
        float x = t[threadIdx.x][threadIdx.y + p*8];
        __nv_bfloat16 h, l; cvt2(x, h, l);
        long o = (long)b * HH * TE + (long)d * TE + j0 + threadIdx.x;
        g_ETh[o] = h; g_ETl[o] = l;
    }
}

// ---------------------------------------------------------------------------
// hi/lo bf16 GEMM, C = A @ B^T, A/B K-contiguous bf16 pairs.
// CTA tile 64 x NT, BK=32, 256 threads (8 warps 2x4), cp.async double-buffered.
// MODE 0: C1 = acc (+bias[col]); Exh/Exl = hilo(exp(C1))
// MODE 1: raw partial -> C1 + kz*partStride   (direct wmma gmem store)
// MINB: min blocks per SM (register cap) — 3 for the big GEMM.
// ---------------------------------------------------------------------------
template<int NT, int MODE, int SPLITK, int MINB>
__global__ void __launch_bounds__(256, MINB) gemm_hl(
    const __nv_bfloat16* __restrict__ Ah, const __nv_bfloat16* __restrict__ Al, int lda, long sA,
    const __nv_bfloat16* __restrict__ Bh, const __nv_bfloat16* __restrict__ Bl, int ldb, long sB,
    float* __restrict__ C1, int ldc, long sC, long partStride,
    __nv_bfloat16* __restrict__ Exh, __nv_bfloat16* __restrict__ Exl,
    int K, const float* __restrict__ bias)
{
    constexpr int BKP = 40;
    constexpr int NJ  = NT / 64;            // b-frags per warp
    extern __shared__ __align__(16) char dsm[];
    __nv_bfloat16* As = reinterpret_cast<__nv_bfloat16*>(dsm);   // [2 stg][2 hl][64*BKP]
    __nv_bfloat16* Bs = As + 2*2*64*BKP;                         // [2 stg][2 hl][NT*BKP]
    float* Cs = reinterpret_cast<float*>(dsm);

    const int tid = threadIdx.x;
    const int wid = tid >> 5, wr = wid >> 2, wc = wid & 3;
    const int z  = blockIdx.z;
    const int bb = z / SPLITK, kz = z % SPLITK;
    const int Ks = K / SPLITK, kbase = kz * Ks, nslab = Ks / 32;

    const __nv_bfloat16* Ah0 = Ah + (long)bb*sA + (long)(blockIdx.y*64)*lda + kbase;
    const __nv_bfloat16* Al0 = Al + (long)bb*sA + (long)(blockIdx.y*64)*lda + kbase;
    const __nv_bfloat16* Bh0 = Bh + (long)bb*sB + (long)(blockIdx.x*NT)*ldb + kbase;
    const __nv_bfloat16* Bl0 = Bl + (long)bb*sB + (long)(blockIdx.x*NT)*ldb + kbase;

    const int ar = tid >> 2, ac = (tid & 3) * 8;

    wmma::fragment<wmma::accumulator, 16, 16, 16, float> acc[2][NJ];
    #pragma unroll
    for (int i = 0; i < 2; ++i)
        #pragma unroll
        for (int j = 0; j < NJ; ++j)
            wmma::fill_fragment(acc[i][j], 0.0f);

    // stage(d, k0)
    #define STAGE(d, k0) do {                                                          \
        cpa16(s2u(As + ((d)*2+0)*64*BKP + ar*BKP + ac), Ah0 + (long)ar*lda + (k0) + ac); \
        cpa16(s2u(As + ((d)*2+1)*64*BKP + ar*BKP + ac), Al0 + (long)ar*lda + (k0) + ac); \
        _Pragma("unroll")                                                              \
        for (int p = 0; p < NT/64; ++p) {                                              \
            int br = ar + p*64;                                                        \
            cpa16(s2u(Bs + ((d)*2+0)*NT*BKP + br*BKP + ac), Bh0 + (long)br*ldb + (k0) + ac); \
            cpa16(s2u(Bs + ((d)*2+1)*NT*BKP + br*BKP + ac), Bl0 + (long)br*ldb + (k0) + ac); \
        }                                                                              \
    } while (0)

    STAGE(0, 0);
    CP_COMMIT();

    for (int s = 0; s < nslab; ++s) {
        const int d = s & 1;
        if (s + 1 < nslab) {
            STAGE(1 - d, (s + 1) * 32);
            CP_COMMIT();
            CP_WAIT1();
        } else {
            CP_WAIT0();
        }
        __syncthreads();

        const __nv_bfloat16* a_h = As + (d*2+0)*64*BKP;
        const __nv_bfloat16* a_l = As + (d*2+1)*64*BKP;
        const __nv_bfloat16* b_h = Bs + (d*2+0)*NT*BKP;
        const __nv_bfloat16* b_l = Bs + (d*2+1)*NT*BKP;

        #pragma unroll
        for (int k2 = 0; k2 < 32; k2 += 16) {
            wmma::fragment<wmma::matrix_a, 16, 16, 16, __nv_bfloat16, wmma::row_major> fah[2], fal[2];
            #pragma unroll
            for (int i = 0; i < 2; ++i) {
                wmma::load_matrix_sync(fah[i], a_h + (wr*32 + 16*i)*BKP + k2, BKP);
                wmma::load_matrix_sync(fal[i], a_l + (wr*32 + 16*i)*BKP + k2, BKP);
            }
            // process B one j at a time to shrink live register set
            #pragma unroll
            for (int j = 0; j < NJ; ++j) {
                wmma::fragment<wmma::matrix_b, 16, 16, 16, __nv_bfloat16, wmma::col_major> fbh, fbl;
                wmma::load_matrix_sync(fbh, b_h + (wc*(NT/4) + 16*j)*BKP + k2, BKP);
                wmma::load_matrix_sync(fbl, b_l + (wc*(NT/4) + 16*j)*BKP + k2, BKP);
                #pragma unroll
                for (int i = 0; i < 2; ++i) {
                    wmma::mma_sync(acc[i][j], fah[i], fbh, acc[i][j]);
                    wmma::mma_sync(acc[i][j], fah[i], fbl, acc[i][j]);
                    wmma::mma_sync(acc[i][j], fal[i], fbh, acc[i][j]);
                }
            }
        }
        __syncthreads();
    }
    #undef STAGE

    const int m0 = blockIdx.y * 64, n0 = blockIdx.x * NT;

    if (MODE == 1) {
        float* Cp = C1 + (long)kz * partStride + (long)bb * sC;
        #pragma unroll
        for (int i = 0; i < 2; ++i)
            #pragma unroll
            for (int j = 0; j < NJ; ++j)
                wmma::store_matrix_sync(
                    &Cp[(long)(m0 + wr*32 + 16*i) * ldc + n0 + wc*(NT/4) + 16*j],
                    acc[i][j], ldc, wmma::mem_row_major);
    } else {
        #pragma unroll
        for (int i = 0; i < 2; ++i)
            #pragma unroll
            for (int j = 0; j < NJ; ++j)
                wmma::store_matrix_sync(&Cs[(wr*32 + 16*i)*(NT+4) + wc*(NT/4) + 16*j],
                                        acc[i][j], NT+4, wmma::mem_row_major);
        __syncthreads();
        #pragma unroll
        for (int q = 0; q < (64*NT)/1024; ++q) {
            int idx = (tid + q*256) * 4;
            int r = idx / NT, c = idx % NT;
            float4 vv = *reinterpret_cast<float4*>(&Cs[r*(NT+4) + c]);
            if (bias) {
                vv.x += bias[n0 + c + 0]; vv.y += bias[n0 + c + 1];
                vv.z += bias[n0 + c + 2]; vv.w += bias[n0 + c + 3];
            }
            long gi = (long)bb*sC + (long)(m0 + r)*ldc + n0 + c;
            *reinterpret_cast<float4*>(&C1[gi]) = vv;
            __nv_bfloat16 h0,h1,h2,h3,l0,l1,l2,l3;
            cvt2(expf(vv.x),h0,l0); cvt2(expf(vv.y),h1,l1);
            cvt2(expf(vv.z),h2,l2); cvt2(expf(vv.w),h3,l3);
            reinterpret_cast<__nv_bfloat162*>(&Exh[gi])[0] = __nv_bfloat162(h0,h1);
            reinterpret_cast<__nv_bfloat162*>(&Exh[gi])[1] = __nv_bfloat162(h2,h3);
            reinterpret_cast<__nv_bfloat162*>(&Exl[gi])[0] = __nv_bfloat162(l0,l1);
            reinterpret_cast<__nv_bfloat162*>(&Exl[gi])[1] = __nv_bfloat162(l2,l3);
        }
    }
}

// ---------------------------------------------------------------------------
__global__ void __launch_bounds__(256) colsum(
    const float* __restrict__ enc, const float* __restrict__ v,
    float* __restrict__ S1, float* __restrict__ S2)
{
    const int b    = blockIdx.y;
    const int lane = threadIdx.x & 31;
    const int jg   = threadIdx.x >> 5;
    const int d    = blockIdx.x * 32 + lane;
    const float* e  = enc + (long)b * TE * HH + d;
    const float* vv = v   + (long)b * TE * HH + d;
    float s1 = 0.f, s2 = 0.f;
    #pragma unroll 8
    for (int j = jg; j < TE; j += 8) {
        float ev = e[(long)j * HH];
        s1 += ev;
        s2 += vv[(long)j * HH] * ev;
    }
    __shared__ float sh1[8][32], sh2[8][32];
    sh1[jg][lane] = s1; sh2[jg][lane] = s2;
    __syncthreads();
    if (jg == 0) {
        float t1 = 0.f, t2 = 0.f;
        #pragma unroll
        for (int g = 0; g < 8; ++g) { t1 += sh1[g][lane]; t2 += sh2[g][lane]; }
        S1[b*HH + d] = t1;
        S2[b*HH + d] = t2;
    }
}

// lse = log(p0+p1) -> hi/lo bf16
__global__ void __launch_bounds__(256) lse_comb(
    const float* __restrict__ p0, const float* __restrict__ p1)
{
    int i = (blockIdx.x * 256 + threadIdx.x) * 4;
    float4 a = *reinterpret_cast<const float4*>(&p0[i]);
    float4 b = *reinterpret_cast<const float4*>(&p1[i]);
    __nv_bfloat16 h0,h1,h2,h3,l0,l1,l2,l3;
    cvt2(logf(a.x + b.x), h0,l0); cvt2(logf(a.y + b.y), h1,l1);
    cvt2(logf(a.z + b.z), h2,l2); cvt2(logf(a.w + b.w), h3,l3);
    reinterpret_cast<__nv_bfloat162*>(&g_Lh[i])[0] = __nv_bfloat162(h0,h1);
    reinterpret_cast<__nv_bfloat162*>(&g_Lh[i])[1] = __nv_bfloat162(h2,h3);
    reinterpret_cast<__nv_bfloat162*>(&g_Ll[i])[0] = __nv_bfloat162(l0,l1);
    reinterpret_cast<__nv_bfloat162*>(&g_Ll[i])[1] = __nv_bfloat162(l2,l3);
}

// out = u*S1 + S2 - (q0+q1)
__global__ void __launch_bounds__(256) final_comb(
    const float* __restrict__ q0, const float* __restrict__ q1,
    const float* __restrict__ u,
    const float* __restrict__ S1, const float* __restrict__ S2,
    float* __restrict__ out)
{
    int i = (blockIdx.x * 256 + threadIdx.x) * 4;
    int b = i >> 15;
    int d = i & (HH - 1);
    float4 a = *reinterpret_cast<const float4*>(&q0[i]);
    float4 c = *reinterpret_cast<const float4*>(&q1[i]);
    float4 uu = *reinterpret_cast<const float4*>(&u[i]);
    float4 s1 = *reinterpret_cast<const float4*>(&S1[b*HH + d]);
    float4 s2 = *reinterpret_cast<const float4*>(&S2[b*HH + d]);
    float4 o;
    o.x = uu.x*s1.x + s2.x - (a.x + c.x);
    o.y = uu.y*s1.y + s2.y - (a.y + c.y);
    o.z = uu.z*s1.z + s2.z - (a.z + c.z);
    o.w = uu.w*s1.w + s2.w - (a.w + c.w);
    *reinterpret_cast<float4*>(&out[i]) = o;
}

// ---------------------------------------------------------------------------
extern "C" void kernel_launch(void* const* d_in, const int* in_sizes, int n_in,
                              void* d_out, int out_size)
{
    const float *enc = nullptr, *dec = nullptr, *W = nullptr, *bias = nullptr;
    for (int i = 0; i < n_in; ++i) {
        switch (in_sizes[i]) {
            case BSZ*TE*HH: enc  = (const float*)d_in[i]; break;
            case BSZ*TD*HH: dec  = (const float*)d_in[i]; break;
            case HH*2*HH:   W    = (const float*)d_in[i]; break;
            case HH:        bias = (const float*)d_in[i]; break;
        }
    }
    float* out = (float*)d_out;

    float *u,*v,*S1,*S2,*pA;
    __nv_bfloat16 *Wh,*Wl,*Dh,*Dl,*Enh,*Enl,*ETh,*ETl,*Euh,*Eul,*Evh,*Evl,*Lh,*Ll;
    cudaGetSymbolAddress((void**)&u,   g_u);
    cudaGetSymbolAddress((void**)&v,   g_v);
    cudaGetSymbolAddress((void**)&S1,  g_S1);
    cudaGetSymbolAddress((void**)&S2,  g_S2);
    cudaGetSymbolAddress((void**)&pA,  g_pA);
    cudaGetSymbolAddress((void**)&Wh,  g_Wh);  cudaGetSymbolAddress((void**)&Wl,  g_Wl);
    cudaGetSymbolAddress((void**)&Dh,  g_Dh);  cudaGetSymbolAddress((void**)&Dl,  g_Dl);
    cudaGetSymbolAddress((void**)&Enh, g_Enh); cudaGetSymbolAddress((void**)&Enl, g_Enl);
    cudaGetSymbolAddress((void**)&ETh, g_ETh); cudaGetSymbolAddress((void**)&ETl, g_ETl);
    cudaGetSymbolAddress((void**)&Euh, g_Euh); cudaGetSymbolAddress((void**)&Eul, g_Eul);
    cudaGetSymbolAddress((void**)&Evh, g_Evh); cudaGetSymbolAddress((void**)&Evl, g_Evl);
    cudaGetSymbolAddress((void**)&Lh,  g_Lh);  cudaGetSymbolAddress((void**)&Ll,  g_Ll);

    constexpr int SMB64  = (64 + 64)  * 40 * 2 * 2 * 2;   // 40960
    constexpr int SMB128 = (64 + 128) * 40 * 2 * 2 * 2;   // 61440
    cudaFuncSetAttribute(gemm_hl<128,0,1,3>, cudaFuncAttributeMaxDynamicSharedMemorySize, SMB128);

    // 0) convert W, dec, enc to hi/lo bf16; build encT
    cvt_all<<<(N_W + N_D + N_E) / 1024, 256>>>(W, dec, enc);
    encT_k<<<dim3(HH/32, TE/32, BSZ), dim3(32, 8)>>>(enc);

    // 1) u = dec @ W_dec^T + bias ; Eu = exp(u)   (M = 512 batch-folded)
    gemm_hl<64,0,1,1><<<dim3(HH/64, (BSZ*TD)/64, 1), 256, SMB64>>>(
        Dh, Dl, HH, 0L,  Wh, Wl, 2*HH, 0L,
        u, HH, 0L, 0L,  Euh, Eul, HH, bias);

    // 2) v = enc @ W_enc^T ; Ev = exp(v)          (M = 4096 batch-folded, 3 CTAs/SM)
    gemm_hl<128,0,1,3><<<dim3(HH/128, (BSZ*TE)/64, 1), 256, SMB128>>>(
        Enh, Enl, HH, 0L,  Wh + HH, Wl + HH, 2*HH, 0L,
        v, HH, 0L, 0L,  Evh, Evl, HH, nullptr);

    // 3) column sums
    colsum<<<dim3(HH/32, BSZ), 256>>>(enc, v, S1, S2);

    // 4) P[b,i,j] = Eu . Ev   (split-K=2 raw partials)
    gemm_hl<64,1,2,1><<<dim3(TE/64, 1, BSZ*2), 256, SMB64>>>(
        Euh, Eul, HH, (long)TD*HH,  Evh, Evl, HH, (long)TE*HH,
        pA, TE, (long)TD*TE, (long)BSZ*TD*TE,  nullptr, nullptr, HH, nullptr);

    // 5) lse = log(P0+P1) -> hi/lo bf16
    lse_comb<<<(BSZ*TD*TE)/1024, 256>>>(pA, pA + BSZ*TD*TE);

    // 6) Q[b,i,d] = lse @ encT^T  (split-K=2 raw partials, reuse pA)
    gemm_hl<64,1,2,1><<<dim3(HH/64, 1, BSZ*2), 256, SMB64>>>(
        Lh, Ll, TE, (long)TD*TE,  ETh, ETl, TE, (long)HH*TE,
        pA, HH, (long)TD*HH, (long)BSZ*TD*HH,  nullptr, nullptr, TE, nullptr);

    // 7) out = u*S1 + S2 - (Q0+Q1)
    final_comb<<<(BSZ*TD*HH)/1024, 256>>>(pA, pA + BSZ*TD*HH, u, S1, S2, out);
}

// round 9
// speedup vs baseline: 1.1763x; 1.1763x over previous
#include <cuda_runtime.h>
#include <cuda_bf16.h>
#include <mma.h>
#include <math.h>
#include <cstdint>

using namespace nvcuda;

#define BSZ 8
#define TD  64
#define TE  512
#define HH  512

// fp32 scratch
__device__ float g_u [BSZ*TD*HH];
__device__ float g_v [BSZ*TE*HH];
__device__ float g_S1[BSZ*HH];
__device__ float g_S2[BSZ*HH];
__device__ float g_pA[4*BSZ*TD*TE];          // split-K=4 raw partials (reused)

// bf16 hi/lo scratch
__device__ __nv_bfloat16 g_Wh [HH*2*HH],  g_Wl [HH*2*HH];
__device__ __nv_bfloat16 g_Dh [BSZ*TD*HH], g_Dl [BSZ*TD*HH];   // dec
__device__ __nv_bfloat16 g_Enh[BSZ*TE*HH], g_Enl[BSZ*TE*HH];   // enc
__device__ __nv_bfloat16 g_ETh[BSZ*HH*TE], g_ETl[BSZ*HH*TE];   // enc transposed [b,d,j]
__device__ __nv_bfloat16 g_Euh[BSZ*TD*HH], g_Eul[BSZ*TD*HH];
__device__ __nv_bfloat16 g_Evh[BSZ*TE*HH], g_Evl[BSZ*TE*HH];
__device__ __nv_bfloat16 g_Lh [BSZ*TD*TE], g_Ll [BSZ*TD*TE];   // lse hi/lo

__device__ __forceinline__ void cvt2(float x, __nv_bfloat16& h, __nv_bfloat16& l) {
    h = __float2bfloat16(x);
    l = __float2bfloat16(x - __bfloat162float(h));
}

__device__ __forceinline__ unsigned int s2u(const void* p) {
    return (unsigned int)__cvta_generic_to_shared(p);
}
__device__ __forceinline__ void cpa16(unsigned int d, const void* s) {
    asm volatile("cp.async.cg.shared.global [%0], [%1], 16;\n" :: "r"(d), "l"(s));
}
#define CP_COMMIT() asm volatile("cp.async.commit_group;\n" ::: "memory")
#define CP_WAIT0()  asm volatile("cp.async.wait_group 0;\n" ::: "memory")
#define CP_WAIT1()  asm volatile("cp.async.wait_group 1;\n" ::: "memory")

// ---------------------------------------------------------------------------
// Convert W, dec, enc to hi/lo bf16 (flat, one pass).
// ---------------------------------------------------------------------------
#define N_W   (HH*2*HH)          // 524288
#define N_D   (BSZ*TD*HH)        // 262144
#define N_E   (BSZ*TE*HH)        // 2097152
__global__ void __launch_bounds__(256) cvt_all(
    const float* __restrict__ W, const float* __restrict__ dec,
    const float* __restrict__ enc)
{
    long i = ((long)blockIdx.x * 256 + threadIdx.x) * 4;
    const float* src; __nv_bfloat16 *H, *L;
    if (i < N_W)            { src = W   + i;              H = g_Wh  + i;              L = g_Wl  + i; }
    else if (i < N_W + N_D) { long o = i - N_W;   src = dec + o; H = g_Dh + o;  L = g_Dl + o; }
    else                    { long o = i - N_W - N_D; src = enc + o; H = g_Enh + o; L = g_Enl + o; }
    float4 x = *reinterpret_cast<const float4*>(src);
    __nv_bfloat16 h0,h1,h2,h3,l0,l1,l2,l3;
    cvt2(x.x,h0,l0); cvt2(x.y,h1,l1); cvt2(x.z,h2,l2); cvt2(x.w,h3,l3);
    reinterpret_cast<__nv_bfloat162*>(H)[0] = __nv_bfloat162(h0,h1);
    reinterpret_cast<__nv_bfloat162*>(H)[1] = __nv_bfloat162(h2,h3);
    reinterpret_cast<__nv_bfloat162*>(L)[0] = __nv_bfloat162(l0,l1);
    reinterpret_cast<__nv_bfloat162*>(L)[1] = __nv_bfloat162(l2,l3);
}

// enc [b,j,d] -> encT hi/lo [b,d,j]
__global__ void encT_k(const float* __restrict__ enc)
{
    __shared__ float t[32][33];
    const int b = blockIdx.z;
    const int j0 = blockIdx.y * 32, d0 = blockIdx.x * 32;
    const float* e = enc + (long)b * TE * HH;
    #pragma unroll
    for (int p = 0; p < 4; ++p)
        t[threadIdx.y + p*8][threadIdx.x] =
            e[(long)(j0 + threadIdx.y + p*8) * HH + d0 + threadIdx.x];
    __syncthreads();
    #pragma unroll
    for (int p = 0; p < 4; ++p) {
        int d = d0 + threadIdx.y + p*8;
        float x = t[threadIdx.x][threadIdx.y + p*8];
        __nv_bfloat16 h, l; cvt2(x, h, l);
        long o = (long)b * HH * TE + (long)d * TE + j0 + threadIdx.x;
        g_ETh[o] = h; g_ETl[o] = l;
    }
}

// ---------------------------------------------------------------------------
// hi/lo bf16 GEMM body, C = A @ B^T, 64x64 CTA tile, BK=32, 256 threads
// (8 warps, 2x4; warp tile 32x16), cp.async double-buffered.
// MODE 0: C1 = acc (+bias[col]); Exh/Exl = hilo(exp(C1))
// MODE 1: raw partial -> C1 + kz*partStride (direct wmma gmem store)
// ---------------------------------------------------------------------------
template<int MODE, int SPLITK>
__device__ __forceinline__ void gemm_body(
    char* dsm,
    const __nv_bfloat16* Ah, const __nv_bfloat16* Al, int lda, long sA,
    const __nv_bfloat16* Bh, const __nv_bfloat16* Bl, int ldb, long sB,
    float* C1, int ldc, long sC, long partStride,
    __nv_bfloat16* Exh, __nv_bfloat16* Exl,
    int K, const float* bias,
    int bx, int by, int bz)
{
    constexpr int BKP = 40;
    __nv_bfloat16* As = reinterpret_cast<__nv_bfloat16*>(dsm);   // [2 stg][2 hl][64*BKP]
    __nv_bfloat16* Bs = As + 2*2*64*BKP;
    float* Cs = reinterpret_cast<float*>(dsm);

    const int tid = threadIdx.x;
    const int wid = tid >> 5, wr = wid >> 2, wc = wid & 3;
    const int bb = bz / SPLITK, kz = bz % SPLITK;
    const int Ks = K / SPLITK, kbase = kz * Ks, nslab = Ks / 32;

    const __nv_bfloat16* Ah0 = Ah + (long)bb*sA + (long)(by*64)*lda + kbase;
    const __nv_bfloat16* Al0 = Al + (long)bb*sA + (long)(by*64)*lda + kbase;
    const __nv_bfloat16* Bh0 = Bh + (long)bb*sB + (long)(bx*64)*ldb + kbase;
    const __nv_bfloat16* Bl0 = Bl + (long)bb*sB + (long)(bx*64)*ldb + kbase;

    const int ar = tid >> 2, ac = (tid & 3) * 8;

    wmma::fragment<wmma::accumulator, 16, 16, 16, float> acc[2];
    wmma::fill_fragment(acc[0], 0.0f);
    wmma::fill_fragment(acc[1], 0.0f);

    #define STAGE(d, k0) do {                                                            \
        cpa16(s2u(As + ((d)*2+0)*64*BKP + ar*BKP + ac), Ah0 + (long)ar*lda + (k0) + ac); \
        cpa16(s2u(As + ((d)*2+1)*64*BKP + ar*BKP + ac), Al0 + (long)ar*lda + (k0) + ac); \
        cpa16(s2u(Bs + ((d)*2+0)*64*BKP + ar*BKP + ac), Bh0 + (long)ar*ldb + (k0) + ac); \
        cpa16(s2u(Bs + ((d)*2+1)*64*BKP + ar*BKP + ac), Bl0 + (long)ar*ldb + (k0) + ac); \
    } while (0)

    STAGE(0, 0);
    CP_COMMIT();

    for (int s = 0; s < nslab; ++s) {
        const int d = s & 1;
        if (s + 1 < nslab) {
            STAGE(1 - d, (s + 1) * 32);
            CP_COMMIT();
            CP_WAIT1();
        } else {
            CP_WAIT0();
        }
        __syncthreads();

        const __nv_bfloat16* a_h = As + (d*2+0)*64*BKP;
        const __nv_bfloat16* a_l = As + (d*2+1)*64*BKP;
        const __nv_bfloat16* b_h = Bs + (d*2+0)*64*BKP;
        const __nv_bfloat16* b_l = Bs + (d*2+1)*64*BKP;

        #pragma unroll
        for (int k2 = 0; k2 < 32; k2 += 16) {
            wmma::fragment<wmma::matrix_a, 16, 16, 16, __nv_bfloat16, wmma::row_major> fah[2], fal[2];
            wmma::fragment<wmma::matrix_b, 16, 16, 16, __nv_bfloat16, wmma::col_major> fbh, fbl;
            #pragma unroll
            for (int i = 0; i < 2; ++i) {
                wmma::load_matrix_sync(fah[i], a_h + (wr*32 + 16*i)*BKP + k2, BKP);
                wmma::load_matrix_sync(fal[i], a_l + (wr*32 + 16*i)*BKP + k2, BKP);
            }
            wmma::load_matrix_sync(fbh, b_h + (wc*16)*BKP + k2, BKP);
            wmma::load_matrix_sync(fbl, b_l + (wc*16)*BKP + k2, BKP);
            #pragma unroll
            for (int i = 0; i < 2; ++i) {
                wmma::mma_sync(acc[i], fah[i], fbh, acc[i]);
                wmma::mma_sync(acc[i], fah[i], fbl, acc[i]);
                wmma::mma_sync(acc[i], fal[i], fbh, acc[i]);
            }
        }
        __syncthreads();
    }
    #undef STAGE

    const int m0 = by * 64, n0 = bx * 64;

    if (MODE == 1) {
        float* Cp = C1 + (long)kz * partStride + (long)bb * sC;
        #pragma unroll
        for (int i = 0; i < 2; ++i)
            wmma::store_matrix_sync(
                &Cp[(long)(m0 + wr*32 + 16*i) * ldc + n0 + wc*16],
                acc[i], ldc, wmma::mem_row_major);
    } else {
        #pragma unroll
        for (int i = 0; i < 2; ++i)
            wmma::store_matrix_sync(&Cs[(wr*32 + 16*i)*68 + wc*16],
                                    acc[i], 68, wmma::mem_row_major);
        __syncthreads();
        #pragma unroll
        for (int q = 0; q < 4; ++q) {
            int idx = (tid + q*256) * 4;
            int r = idx >> 6, c = idx & 63;
            float4 vv = *reinterpret_cast<float4*>(&Cs[r*68 + c]);
            if (bias) {
                vv.x += bias[n0 + c + 0]; vv.y += bias[n0 + c + 1];
                vv.z += bias[n0 + c + 2]; vv.w += bias[n0 + c + 3];
            }
            long gi = (long)bb*sC + (long)(m0 + r)*ldc + n0 + c;
            *reinterpret_cast<float4*>(&C1[gi]) = vv;
            __nv_bfloat16 h0,h1,h2,h3,l0,l1,l2,l3;
            cvt2(expf(vv.x),h0,l0); cvt2(expf(vv.y),h1,l1);
            cvt2(expf(vv.z),h2,l2); cvt2(expf(vv.w),h3,l3);
            reinterpret_cast<__nv_bfloat162*>(&Exh[gi])[0] = __nv_bfloat162(h0,h1);
            reinterpret_cast<__nv_bfloat162*>(&Exh[gi])[1] = __nv_bfloat162(h2,h3);
            reinterpret_cast<__nv_bfloat162*>(&Exl[gi])[0] = __nv_bfloat162(l0,l1);
            reinterpret_cast<__nv_bfloat162*>(&Exl[gi])[1] = __nv_bfloat162(l2,l3);
        }
    }
}

// Fused GEMM1 (y<8: u = dec@W_dec^T + bias) + GEMM2 (y>=8: v = enc@W_enc^T),
// both batch-folded, with exp epilogues. grid (8, 72).
__global__ void __launch_bounds__(256, 3) gemm12_k(const float* __restrict__ bias)
{
    extern __shared__ char dsm[];
    if (blockIdx.y < 8)
        gemm_body<0,1>(dsm, g_Dh, g_Dl, HH, 0L, g_Wh, g_Wl, 2*HH, 0L,
                       g_u, HH, 0L, 0L, g_Euh, g_Eul, HH, bias,
                       blockIdx.x, blockIdx.y, 0);
    else
        gemm_body<0,1>(dsm, g_Enh, g_Enl, HH, 0L, g_Wh + HH, g_Wl + HH, 2*HH, 0L,
                       g_v, HH, 0L, 0L, g_Evh, g_Evl, HH, nullptr,
                       blockIdx.x, blockIdx.y - 8, 0);
}

// P[b,i,j] = Eu[b,i,:] . Ev[b,j,:]  raw partials, split-K=4. grid (8,1,32).
__global__ void __launch_bounds__(256) gemm4_k()
{
    extern __shared__ char dsm[];
    gemm_body<1,4>(dsm, g_Euh, g_Eul, HH, (long)TD*HH, g_Evh, g_Evl, HH, (long)TE*HH,
                   g_pA, TE, (long)TD*TE, (long)BSZ*TD*TE, nullptr, nullptr, HH, nullptr,
                   blockIdx.x, 0, blockIdx.z);
}

// Q[b,i,d] = lse[b,i,:] . encT[b,d,:]  raw partials, split-K=4. grid (8,1,32).
__global__ void __launch_bounds__(256) gemm6_k()
{
    extern __shared__ char dsm[];
    gemm_body<1,4>(dsm, g_Lh, g_Ll, TE, (long)TD*TE, g_ETh, g_ETl, TE, (long)HH*TE,
                   g_pA, HH, (long)TD*HH, (long)BSZ*TD*HH, nullptr, nullptr, TE, nullptr,
                   blockIdx.x, 0, blockIdx.z);
}

// ---------------------------------------------------------------------------
__global__ void __launch_bounds__(256) colsum(
    const float* __restrict__ enc, const float* __restrict__ v,
    float* __restrict__ S1, float* __restrict__ S2)
{
    const int b    = blockIdx.y;
    const int lane = threadIdx.x & 31;
    const int jg   = threadIdx.x >> 5;
    const int d    = blockIdx.x * 32 + lane;
    const float* e  = enc + (long)b * TE * HH + d;
    const float* vv = v   + (long)b * TE * HH + d;
    float s1 = 0.f, s2 = 0.f;
    #pragma unroll 8
    for (int j = jg; j < TE; j += 8) {
        float ev = e[(long)j * HH];
        s1 += ev;
        s2 += vv[(long)j * HH] * ev;
    }
    __shared__ float sh1[8][32], sh2[8][32];
    sh1[jg][lane] = s1; sh2[jg][lane] = s2;
    __syncthreads();
    if (jg == 0) {
        float t1 = 0.f, t2 = 0.f;
        #pragma unroll
        for (int g = 0; g < 8; ++g) { t1 += sh1[g][lane]; t2 += sh2[g][lane]; }
        S1[b*HH + d] = t1;
        S2[b*HH + d] = t2;
    }
}

// lse = log(sum of 4 partials) -> hi/lo bf16
__global__ void __launch_bounds__(256) lse_comb(const float* __restrict__ p)
{
    const long N = (long)BSZ*TD*TE;
    long i = ((long)blockIdx.x * 256 + threadIdx.x) * 4;
    float4 a = *reinterpret_cast<const float4*>(&p[i]);
    float4 b = *reinterpret_cast<const float4*>(&p[i + N]);
    float4 c = *reinterpret_cast<const float4*>(&p[i + 2*N]);
    float4 e = *reinterpret_cast<const float4*>(&p[i + 3*N]);
    __nv_bfloat16 h0,h1,h2,h3,l0,l1,l2,l3;
    cvt2(logf((a.x+b.x)+(c.x+e.x)), h0,l0);
    cvt2(logf((a.y+b.y)+(c.y+e.y)), h1,l1);
    cvt2(logf((a.z+b.z)+(c.z+e.z)), h2,l2);
    cvt2(logf((a.w+b.w)+(c.w+e.w)), h3,l3);
    reinterpret_cast<__nv_bfloat162*>(&g_Lh[i])[0] = __nv_bfloat162(h0,h1);
    reinterpret_cast<__nv_bfloat162*>(&g_Lh[i])[1] = __nv_bfloat162(h2,h3);
    reinterpret_cast<__nv_bfloat162*>(&g_Ll[i])[0] = __nv_bfloat162(l0,l1);
    reinterpret_cast<__nv_bfloat162*>(&g_Ll[i])[1] = __nv_bfloat162(l2,l3);
}

// out = u*S1 + S2 - sum of 4 partials
__global__ void __launch_bounds__(256) final_comb(
    const float* __restrict__ p, const float* __restrict__ u,
    const float* __restrict__ S1, const float* __restrict__ S2,
    float* __restrict__ out)
{
    const long N = (long)BSZ*TD*HH;
    long i = ((long)blockIdx.x * 256 + threadIdx.x) * 4;
    int b = (int)(i >> 15);
    int d = (int)(i & (HH - 1));
    float4 a = *reinterpret_cast<const float4*>(&p[i]);
    float4 c = *reinterpret_cast<const float4*>(&p[i + N]);
    float4 e = *reinterpret_cast<const float4*>(&p[i + 2*N]);
    float4 f = *reinterpret_cast<const float4*>(&p[i + 3*N]);
    float4 uu = *reinterpret_cast<const float4*>(&u[i]);
    float4 s1 = *reinterpret_cast<const float4*>(&S1[b*HH + d]);
    float4 s2 = *reinterpret_cast<const float4*>(&S2[b*HH + d]);
    float4 o;
    o.x = uu.x*s1.x + s2.x - ((a.x+c.x)+(e.x+f.x));
    o.y = uu.y*s1.y + s2.y - ((a.y+c.y)+(e.y+f.y));
    o.z = uu.z*s1.z + s2.z - ((a.z+c.z)+(e.z+f.z));
    o.w = uu.w*s1.w + s2.w - ((a.w+c.w)+(e.w+f.w));
    *reinterpret_cast<float4*>(&out[i]) = o;
}

// ---------------------------------------------------------------------------
extern "C" void kernel_launch(void* const* d_in, const int* in_sizes, int n_in,
                              void* d_out, int out_size)
{
    const float *enc = nullptr, *dec = nullptr, *W = nullptr, *bias = nullptr;
    for (int i = 0; i < n_in; ++i) {
        switch (in_sizes[i]) {
            case BSZ*TE*HH: enc  = (const float*)d_in[i]; break;
            case BSZ*TD*HH: dec  = (const float*)d_in[i]; break;
            case HH*2*HH:   W    = (const float*)d_in[i]; break;
            case HH:        bias = (const float*)d_in[i]; break;
        }
    }
    float* out = (float*)d_out;

    float *u,*v,*S1,*S2,*pA;
    cudaGetSymbolAddress((void**)&u,  g_u);
    cudaGetSymbolAddress((void**)&v,  g_v);
    cudaGetSymbolAddress((void**)&S1, g_S1);
    cudaGetSymbolAddress((void**)&S2, g_S2);
    cudaGetSymbolAddress((void**)&pA, g_pA);

    constexpr int SMB = (64 + 64) * 40 * 2 * 2 * 2;   // 40960

    // 0) convert W, dec, enc to hi/lo bf16; build encT
    cvt_all<<<(N_W + N_D + N_E) / 1024, 256>>>(W, dec, enc);
    encT_k<<<dim3(HH/32, TE/32, BSZ), dim3(32, 8)>>>(enc);

    // 1+2) fused: u = dec@W_dec^T + bias, Eu=exp(u); v = enc@W_enc^T, Ev=exp(v)
    gemm12_k<<<dim3(8, 8 + 64, 1), 256, SMB>>>(bias);

    // 3) column sums
    colsum<<<dim3(HH/32, BSZ), 256>>>(enc, v, S1, S2);

    // 4) P = Eu . Ev partials (split-K=4)
    gemm4_k<<<dim3(8, 1, BSZ*4), 256, SMB>>>();

    // 5) lse = log(sum partials) -> hi/lo bf16
    lse_comb<<<(BSZ*TD*TE)/1024, 256>>>(pA);

    // 6) Q = lse . encT partials (split-K=4)
    gemm6_k<<<dim3(8, 1, BSZ*4), 256, SMB>>>();

    // 7) out = u*S1 + S2 - sum partials
    final_comb<<<(BSZ*TD*HH)/1024, 256>>>(pA, u, S1, S2, out);
}

// round 11
// speedup vs baseline: 1.2175x; 1.0350x over previous
#include <cuda_runtime.h>
#include <cuda_bf16.h>
#include <mma.h>
#include <math.h>
#include <cstdint>

using namespace nvcuda;

#define BSZ 8
#define TD  64
#define TE  512
#define HH  512

// fp32 scratch
__device__ float g_u [BSZ*TD*HH];
__device__ float g_v [BSZ*TE*HH];
__device__ float g_cS1[4*BSZ*HH];            // colsum j-split partials
__device__ float g_cS2[4*BSZ*HH];
__device__ float g_pA[4*BSZ*TD*TE];          // split-K=4 raw partials (reused)

// bf16 hi/lo scratch
__device__ __nv_bfloat16 g_Wh [HH*2*HH],  g_Wl [HH*2*HH];
__device__ __nv_bfloat16 g_Dh [BSZ*TD*HH], g_Dl [BSZ*TD*HH];   // dec
__device__ __nv_bfloat16 g_Enh[BSZ*TE*HH], g_Enl[BSZ*TE*HH];   // enc
__device__ __nv_bfloat16 g_ETh[BSZ*HH*TE], g_ETl[BSZ*HH*TE];   // enc transposed [b,d,j]
__device__ __nv_bfloat16 g_Euh[BSZ*TD*HH], g_Eul[BSZ*TD*HH];
__device__ __nv_bfloat16 g_Evh[BSZ*TE*HH], g_Evl[BSZ*TE*HH];
__device__ __nv_bfloat16 g_Lh [BSZ*TD*TE], g_Ll [BSZ*TD*TE];   // lse hi/lo

__device__ __forceinline__ void cvt2(float x, __nv_bfloat16& h, __nv_bfloat16& l) {
    h = __float2bfloat16(x);
    l = __float2bfloat16(x - __bfloat162float(h));
}

__device__ __forceinline__ unsigned int s2u(const void* p) {
    return (unsigned int)__cvta_generic_to_shared(p);
}
__device__ __forceinline__ void cpa16(unsigned int d, const void* s) {
    asm volatile("cp.async.cg.shared.global [%0], [%1], 16;\n" :: "r"(d), "l"(s));
}
#define CP_COMMIT() asm volatile("cp.async.commit_group;\n" ::: "memory")
#define CP_WAIT0()  asm volatile("cp.async.wait_group 0;\n" ::: "memory")
#define CP_WAIT1()  asm volatile("cp.async.wait_group 1;\n" ::: "memory")

// ---------------------------------------------------------------------------
// Fused prep: blocks [0, NB_CVT) convert W/dec/enc to hi/lo bf16;
// blocks [NB_CVT, NB_CVT+NB_ET) build encT hi/lo [b,d,j].
// ---------------------------------------------------------------------------
#define N_W   (HH*2*HH)          // 524288
#define N_D   (BSZ*TD*HH)        // 262144
#define N_E   (BSZ*TE*HH)        // 2097152
#define NB_CVT ((N_W + N_D + N_E) / 1024)     // 2816
#define NB_ET  ((HH/32)*(TE/32)*BSZ)          // 2048

__global__ void __launch_bounds__(256) prep_k(
    const float* __restrict__ W, const float* __restrict__ dec,
    const float* __restrict__ enc)
{
    const int bid = blockIdx.x;
    const int tid = threadIdx.x;
    if (bid < NB_CVT) {
        long i = ((long)bid * 256 + tid) * 4;
        const float* src; __nv_bfloat16 *H, *L;
        if (i < N_W)            { src = W + i;                    H = g_Wh + i;  L = g_Wl + i; }
        else if (i < N_W + N_D) { long o = i - N_W;       src = dec + o; H = g_Dh + o;  L = g_Dl + o; }
        else                    { long o = i - N_W - N_D; src = enc + o; H = g_Enh + o; L = g_Enl + o; }
        float4 x = *reinterpret_cast<const float4*>(src);
        __nv_bfloat16 h0,h1,h2,h3,l0,l1,l2,l3;
        cvt2(x.x,h0,l0); cvt2(x.y,h1,l1); cvt2(x.z,h2,l2); cvt2(x.w,h3,l3);
        reinterpret_cast<__nv_bfloat162*>(H)[0] = __nv_bfloat162(h0,h1);
        reinterpret_cast<__nv_bfloat162*>(H)[1] = __nv_bfloat162(h2,h3);
        reinterpret_cast<__nv_bfloat162*>(L)[0] = __nv_bfloat162(l0,l1);
        reinterpret_cast<__nv_bfloat162*>(L)[1] = __nv_bfloat162(l2,l3);
    } else {
        __shared__ float t[32][33];
        const int eb  = bid - NB_CVT;
        const int b   = eb >> 8;                  // / 256
        const int rem = eb & 255;
        const int j0  = (rem >> 4) * 32;          // 16 j-tiles
        const int d0  = (rem & 15) * 32;          // 16 d-tiles
        const int tx = tid & 31, ty = tid >> 5;   // (32, 8)
        const float* e = enc + (long)b * TE * HH;
        #pragma unroll
        for (int p = 0; p < 4; ++p)
            t[ty + p*8][tx] = e[(long)(j0 + ty + p*8) * HH + d0 + tx];
        __syncthreads();
        #pragma unroll
        for (int p = 0; p < 4; ++p) {
            int d = d0 + ty + p*8;
            float x = t[tx][ty + p*8];
            __nv_bfloat16 h, l; cvt2(x, h, l);
            long o = (long)b * HH * TE + (long)d * TE + j0 + tx;
            g_ETh[o] = h; g_ETl[o] = l;
        }
    }
}

// ---------------------------------------------------------------------------
// hi/lo bf16 GEMM body, C = A @ B^T, 64x64 CTA tile, BK=32, 256 threads
// (8 warps, 2x4; warp tile 32x16), cp.async double-buffered.
// MODE 0: C1 = acc (+bias[col]); Exh/Exl = hilo(exp(C1))
// MODE 1: raw partial -> C1 + kz*partStride (direct wmma gmem store)
// ---------------------------------------------------------------------------
template<int MODE, int SPLITK>
__device__ __forceinline__ void gemm_body(
    char* dsm,
    const __nv_bfloat16* Ah, const __nv_bfloat16* Al, int lda, long sA,
    const __nv_bfloat16* Bh, const __nv_bfloat16* Bl, int ldb, long sB,
    float* C1, int ldc, long sC, long partStride,
    __nv_bfloat16* Exh, __nv_bfloat16* Exl,
    int K, const float* bias,
    int bx, int by, int bz)
{
    constexpr int BKP = 40;
    __nv_bfloat16* As = reinterpret_cast<__nv_bfloat16*>(dsm);   // [2 stg][2 hl][64*BKP]
    __nv_bfloat16* Bs = As + 2*2*64*BKP;
    float* Cs = reinterpret_cast<float*>(dsm);

    const int tid = threadIdx.x;
    const int wid = tid >> 5, wr = wid >> 2, wc = wid & 3;
    const int bb = bz / SPLITK, kz = bz % SPLITK;
    const int Ks = K / SPLITK, kbase = kz * Ks, nslab = Ks / 32;

    const __nv_bfloat16* Ah0 = Ah + (long)bb*sA + (long)(by*64)*lda + kbase;
    const __nv_bfloat16* Al0 = Al + (long)bb*sA + (long)(by*64)*lda + kbase;
    const __nv_bfloat16* Bh0 = Bh + (long)bb*sB + (long)(bx*64)*ldb + kbase;
    const __nv_bfloat16* Bl0 = Bl + (long)bb*sB + (long)(bx*64)*ldb + kbase;

    const int ar = tid >> 2, ac = (tid & 3) * 8;

    wmma::fragment<wmma::accumulator, 16, 16, 16, float> acc[2];
    wmma::fill_fragment(acc[0], 0.0f);
    wmma::fill_fragment(acc[1], 0.0f);

    #define STAGE(d, k0) do {                                                            \
        cpa16(s2u(As + ((d)*2+0)*64*BKP + ar*BKP + ac), Ah0 + (long)ar*lda + (k0) + ac); \
        cpa16(s2u(As + ((d)*2+1)*64*BKP + ar*BKP + ac), Al0 + (long)ar*lda + (k0) + ac); \
        cpa16(s2u(Bs + ((d)*2+0)*64*BKP + ar*BKP + ac), Bh0 + (long)ar*ldb + (k0) + ac); \
        cpa16(s2u(Bs + ((d)*2+1)*64*BKP + ar*BKP + ac), Bl0 + (long)ar*ldb + (k0) + ac); \
    } while (0)

    STAGE(0, 0);
    CP_COMMIT();

    for (int s = 0; s < nslab; ++s) {
        const int d = s & 1;
        if (s + 1 < nslab) {
            STAGE(1 - d, (s + 1) * 32);
            CP_COMMIT();
            CP_WAIT1();
        } else {
            CP_WAIT0();
        }
        __syncthreads();

        const __nv_bfloat16* a_h = As + (d*2+0)*64*BKP;
        const __nv_bfloat16* a_l = As + (d*2+1)*64*BKP;
        const __nv_bfloat16* b_h = Bs + (d*2+0)*64*BKP;
        const __nv_bfloat16* b_l = Bs + (d*2+1)*64*BKP;

        #pragma unroll
        for (int k2 = 0; k2 < 32; k2 += 16) {
            wmma::fragment<wmma::matrix_a, 16, 16, 16, __nv_bfloat16, wmma::row_major> fah[2], fal[2];
            wmma::fragment<wmma::matrix_b, 16, 16, 16, __nv_bfloat16, wmma::col_major> fbh, fbl;
            #pragma unroll
            for (int i = 0; i < 2; ++i) {
                wmma::load_matrix_sync(fah[i], a_h + (wr*32 + 16*i)*BKP + k2, BKP);
                wmma::load_matrix_sync(fal[i], a_l + (wr*32 + 16*i)*BKP + k2, BKP);
            }
            wmma::load_matrix_sync(fbh, b_h + (wc*16)*BKP + k2, BKP);
            wmma::load_matrix_sync(fbl, b_l + (wc*16)*BKP + k2, BKP);
            #pragma unroll
            for (int i = 0; i < 2; ++i) {
                wmma::mma_sync(acc[i], fah[i], fbh, acc[i]);
                wmma::mma_sync(acc[i], fah[i], fbl, acc[i]);
                wmma::mma_sync(acc[i], fal[i], fbh, acc[i]);
            }
        }
        __syncthreads();
    }
    #undef STAGE

    const int m0 = by * 64, n0 = bx * 64;

    if (MODE == 1) {
        float* Cp = C1 + (long)kz * partStride + (long)bb * sC;
        #pragma unroll
        for (int i = 0; i < 2; ++i)
            wmma::store_matrix_sync(
                &Cp[(long)(m0 + wr*32 + 16*i) * ldc + n0 + wc*16],
                acc[i], ldc, wmma::mem_row_major);
    } else {
        #pragma unroll
        for (int i = 0; i < 2; ++i)
            wmma::store_matrix_sync(&Cs[(wr*32 + 16*i)*68 + wc*16],
                                    acc[i], 68, wmma::mem_row_major);
        __syncthreads();
        #pragma unroll
        for (int q = 0; q < 4; ++q) {
            int idx = (tid + q*256) * 4;
            int r = idx >> 6, c = idx & 63;
            float4 vv = *reinterpret_cast<float4*>(&Cs[r*68 + c]);
            if (bias) {
                vv.x += bias[n0 + c + 0]; vv.y += bias[n0 + c + 1];
                vv.z += bias[n0 + c + 2]; vv.w += bias[n0 + c + 3];
            }
            long gi = (long)bb*sC + (long)(m0 + r)*ldc + n0 + c;
            *reinterpret_cast<float4*>(&C1[gi]) = vv;
            __nv_bfloat16 h0,h1,h2,h3,l0,l1,l2,l3;
            cvt2(expf(vv.x),h0,l0); cvt2(expf(vv.y),h1,l1);
            cvt2(expf(vv.z),h2,l2); cvt2(expf(vv.w),h3,l3);
            reinterpret_cast<__nv_bfloat162*>(&Exh[gi])[0] = __nv_bfloat162(h0,h1);
            reinterpret_cast<__nv_bfloat162*>(&Exh[gi])[1] = __nv_bfloat162(h2,h3);
            reinterpret_cast<__nv_bfloat162*>(&Exl[gi])[0] = __nv_bfloat162(l0,l1);
            reinterpret_cast<__nv_bfloat162*>(&Exl[gi])[1] = __nv_bfloat162(l2,l3);
        }
    }
}

// Fused GEMM1 (y<8: u = dec@W_dec^T + bias) + GEMM2 (y>=8: v = enc@W_enc^T),
// both batch-folded, with exp epilogues. grid (8, 72).
__global__ void __launch_bounds__(256, 3) gemm12_k(const float* __restrict__ bias)
{
    extern __shared__ char dsm[];
    if (blockIdx.y < 8)
        gemm_body<0,1>(dsm, g_Dh, g_Dl, HH, 0L, g_Wh, g_Wl, 2*HH, 0L,
                       g_u, HH, 0L, 0L, g_Euh, g_Eul, HH, bias,
                       blockIdx.x, blockIdx.y, 0);
    else
        gemm_body<0,1>(dsm, g_Enh, g_Enl, HH, 0L, g_Wh + HH, g_Wl + HH, 2*HH, 0L,
                       g_v, HH, 0L, 0L, g_Evh, g_Evl, HH, nullptr,
                       blockIdx.x, blockIdx.y - 8, 0);
}

// ---------------------------------------------------------------------------
// Fused: blocks [0,256) = P[b,i,j] = Eu.Ev split-K=4 raw partials;
//        blocks [256, 256+512) = colsum j-split partials.
// colsum partial g: S1/S2 over j in [g*128, (g+1)*128).
// ---------------------------------------------------------------------------
__global__ void __launch_bounds__(256) gemm4_colsum_k(
    const float* __restrict__ enc)
{
    extern __shared__ char dsm[];
    const int bid = blockIdx.x;
    if (bid < 256) {
        gemm_body<1,4>(dsm, g_Euh, g_Eul, HH, (long)TD*HH, g_Evh, g_Evl, HH, (long)TE*HH,
                       g_pA, TE, (long)TD*TE, (long)BSZ*TD*TE, nullptr, nullptr, HH, nullptr,
                       bid & 7, 0, bid >> 3);
    } else {
        const int cb   = bid - 256;           // 0..511
        const int g    = cb >> 7;             // j-split group 0..3
        const int rem  = cb & 127;
        const int b    = rem >> 4;            // 0..7
        const int dblk = rem & 15;            // 0..15
        const int tid  = threadIdx.x;
        const int lane = tid & 31, jg = tid >> 5;
        const int d    = dblk * 32 + lane;
        const float* e  = enc + (long)b * TE * HH + d;
        const float* vv = g_v + (long)b * TE * HH + d;
        float s1 = 0.f, s2 = 0.f;
        const int j0 = g * 128;
        #pragma unroll 8
        for (int j = j0 + jg; j < j0 + 128; j += 8) {
            float ev = e[(long)j * HH];
            s1 += ev;
            s2 += vv[(long)j * HH] * ev;
        }
        float* sh1 = reinterpret_cast<float*>(dsm);          // [8][32]
        float* sh2 = sh1 + 256;
        sh1[jg*32 + lane] = s1; sh2[jg*32 + lane] = s2;
        __syncthreads();
        if (jg == 0) {
            float t1 = 0.f, t2 = 0.f;
            #pragma unroll
            for (int q = 0; q < 8; ++q) { t1 += sh1[q*32 + lane]; t2 += sh2[q*32 + lane]; }
            g_cS1[g*BSZ*HH + b*HH + d] = t1;
            g_cS2[g*BSZ*HH + b*HH + d] = t2;
        }
    }
}

// Q[b,i,d] = lse[b,i,:] . encT[b,d,:]  raw partials, split-K=4. grid (8,1,32).
__global__ void __launch_bounds__(256) gemm6_k()
{
    extern __shared__ char dsm[];
    gemm_body<1,4>(dsm, g_Lh, g_Ll, TE, (long)TD*TE, g_ETh, g_ETl, TE, (long)HH*TE,
                   g_pA, HH, (long)TD*HH, (long)BSZ*TD*HH, nullptr, nullptr, TE, nullptr,
                   blockIdx.x, 0, blockIdx.z);
}

// lse = log(sum of 4 partials) -> hi/lo bf16
__global__ void __launch_bounds__(256) lse_comb(const float* __restrict__ p)
{
    const long N = (long)BSZ*TD*TE;
    long i = ((long)blockIdx.x * 256 + threadIdx.x) * 4;
    float4 a = *reinterpret_cast<const float4*>(&p[i]);
    float4 b = *reinterpret_cast<const float4*>(&p[i + N]);
    float4 c = *reinterpret_cast<const float4*>(&p[i + 2*N]);
    float4 e = *reinterpret_cast<const float4*>(&p[i + 3*N]);
    __nv_bfloat16 h0,h1,h2,h3,l0,l1,l2,l3;
    cvt2(logf((a.x+b.x)+(c.x+e.x)), h0,l0);
    cvt2(logf((a.y+b.y)+(c.y+e.y)), h1,l1);
    cvt2(logf((a.z+b.z)+(c.z+e.z)), h2,l2);
    cvt2(logf((a.w+b.w)+(c.w+e.w)), h3,l3);
    reinterpret_cast<__nv_bfloat162*>(&g_Lh[i])[0] = __nv_bfloat162(h0,h1);
    reinterpret_cast<__nv_bfloat162*>(&g_Lh[i])[1] = __nv_bfloat162(h2,h3);
    reinterpret_cast<__nv_bfloat162*>(&g_Ll[i])[0] = __nv_bfloat162(l0,l1);
    reinterpret_cast<__nv_bfloat162*>(&g_Ll[i])[1] = __nv_bfloat162(l2,l3);
}

// out = u*(sum cS1) + (sum cS2) - sum of 4 Q partials
__global__ void __launch_bounds__(256) final_comb(
    const float* __restrict__ p, const float* __restrict__ u,
    float* __restrict__ out)
{
    const long N = (long)BSZ*TD*HH;
    long i = ((long)blockIdx.x * 256 + threadIdx.x) * 4;
    int b = (int)(i >> 15);
    int d = (int)(i & (HH - 1));
    float4 a = *reinterpret_cast<const float4*>(&p[i]);
    float4 c = *reinterpret_cast<const float4*>(&p[i + N]);
    float4 e = *reinterpret_cast<const float4*>(&p[i + 2*N]);
    float4 f = *reinterpret_cast<const float4*>(&p[i + 3*N]);
    float4 uu = *reinterpret_cast<const float4*>(&u[i]);
    float4 s1 = make_float4(0.f,0.f,0.f,0.f), s2 = make_float4(0.f,0.f,0.f,0.f);
    #pragma unroll
    for (int g = 0; g < 4; ++g) {
        float4 x1 = *reinterpret_cast<const float4*>(&g_cS1[g*BSZ*HH + b*HH + d]);
        float4 x2 = *reinterpret_cast<const float4*>(&g_cS2[g*BSZ*HH + b*HH + d]);
        s1.x += x1.x; s1.y += x1.y; s1.z += x1.z; s1.w += x1.w;
        s2.x += x2.x; s2.y += x2.y; s2.z += x2.z; s2.w += x2.w;
    }
    float4 o;
    o.x = uu.x*s1.x + s2.x - ((a.x+c.x)+(e.x+f.x));
    o.y = uu.y*s1.y + s2.y - ((a.y+c.y)+(e.y+f.y));
    o.z = uu.z*s1.z + s2.z - ((a.z+c.z)+(e.z+f.z));
    o.w = uu.w*s1.w + s2.w - ((a.w+c.w)+(e.w+f.w));
    *reinterpret_cast<float4*>(&out[i]) = o;
}

// ---------------------------------------------------------------------------
extern "C" void kernel_launch(void* const* d_in, const int* in_sizes, int n_in,
                              void* d_out, int out_size)
{
    const float *enc = nullptr, *dec = nullptr, *W = nullptr, *bias = nullptr;
    for (int i = 0; i < n_in; ++i) {
        switch (in_sizes[i]) {
            case BSZ*TE*HH: enc  = (const float*)d_in[i]; break;
            case BSZ*TD*HH: dec  = (const float*)d_in[i]; break;
            case HH*2*HH:   W    = (const float*)d_in[i]; break;
            case HH:        bias = (const float*)d_in[i]; break;
        }
    }
    float* out = (float*)d_out;

    float *u, *pA;
    cudaGetSymbolAddress((void**)&u,  g_u);
    cudaGetSymbolAddress((void**)&pA, g_pA);

    constexpr int SMB = (64 + 64) * 40 * 2 * 2 * 2;   // 40960

    // 0) convert W, dec, enc to hi/lo bf16 + build encT (fused)
    prep_k<<<NB_CVT + NB_ET, 256>>>(W, dec, enc);

    // 1+2) fused: u = dec@W_dec^T + bias, Eu=exp(u); v = enc@W_enc^T, Ev=exp(v)
    gemm12_k<<<dim3(8, 8 + 64, 1), 256, SMB>>>(bias);

    // 3+4) fused: P = Eu.Ev partials (split-K=4) + colsum j-split partials
    gemm4_colsum_k<<<256 + 512, 256, SMB>>>(enc);

    // 5) lse = log(sum partials) -> hi/lo bf16
    lse_comb<<<(BSZ*TD*TE)/1024, 256>>>(pA);

    // 6) Q = lse . encT partials (split-K=4)
    gemm6_k<<<dim3(8, 1, BSZ*4), 256, SMB>>>();

    // 7) out = u*S1 + S2 - sum partials
    final_comb<<<(BSZ*TD*HH)/1024, 256>>>(pA, u, out);
}

// round 12
// speedup vs baseline: 1.3301x; 1.0925x over previous
#include <cuda_runtime.h>
#include <cuda_bf16.h>
#include <mma.h>
#include <math.h>
#include <cstdint>

using namespace nvcuda;

#define BSZ 8
#define TD  64
#define TE  512
#define HH  512

// fp32 scratch
__device__ float g_u [BSZ*TD*HH];
__device__ float g_v [BSZ*TE*HH];
__device__ float g_cS1[4*BSZ*HH];            // colsum j-split partials
__device__ float g_cS2[4*BSZ*HH];
__device__ float g_pA[4*BSZ*TD*TE];          // split-K=4 raw partials (reused)

// bf16 hi/lo scratch
__device__ __nv_bfloat16 g_Wh [HH*2*HH],  g_Wl [HH*2*HH];
__device__ __nv_bfloat16 g_Dh [BSZ*TD*HH], g_Dl [BSZ*TD*HH];   // dec
__device__ __nv_bfloat16 g_Enh[BSZ*TE*HH], g_Enl[BSZ*TE*HH];   // enc
__device__ __nv_bfloat16 g_ETh[BSZ*HH*TE], g_ETl[BSZ*HH*TE];   // enc transposed [b,d,j]
__device__ __nv_bfloat16 g_Euh[BSZ*TD*HH], g_Eul[BSZ*TD*HH];
__device__ __nv_bfloat16 g_Evh[BSZ*TE*HH], g_Evl[BSZ*TE*HH];
__device__ __nv_bfloat16 g_Lh [BSZ*TD*TE], g_Ll [BSZ*TD*TE];   // lse hi/lo

__device__ __forceinline__ void cvt2(float x, __nv_bfloat16& h, __nv_bfloat16& l) {
    h = __float2bfloat16(x);
    l = __float2bfloat16(x - __bfloat162float(h));
}

__device__ __forceinline__ unsigned int s2u(const void* p) {
    return (unsigned int)__cvta_generic_to_shared(p);
}
__device__ __forceinline__ void cpa16(unsigned int d, const void* s) {
    asm volatile("cp.async.cg.shared.global [%0], [%1], 16;\n" :: "r"(d), "l"(s));
}
#define CP_COMMIT() asm volatile("cp.async.commit_group;\n" ::: "memory")
#define CP_WAIT0()  asm volatile("cp.async.wait_group 0;\n" ::: "memory")
#define CP_WAIT1()  asm volatile("cp.async.wait_group 1;\n" ::: "memory")

// ---------------------------------------------------------------------------
// Fused prep: blocks [0, NB_CVT) convert W/dec/enc to hi/lo bf16;
// blocks [NB_CVT, NB_CVT+NB_ET) build encT hi/lo [b,d,j].
// ---------------------------------------------------------------------------
#define N_W   (HH*2*HH)          // 524288
#define N_D   (BSZ*TD*HH)        // 262144
#define N_E   (BSZ*TE*HH)        // 2097152
#define NB_CVT ((N_W + N_D + N_E) / 1024)     // 2816
#define NB_ET  ((HH/32)*(TE/32)*BSZ)          // 2048

__global__ void __launch_bounds__(256) prep_k(
    const float* __restrict__ W, const float* __restrict__ dec,
    const float* __restrict__ enc)
{
    const int bid = blockIdx.x;
    const int tid = threadIdx.x;
    if (bid < NB_CVT) {
        long i = ((long)bid * 256 + tid) * 4;
        const float* src; __nv_bfloat16 *H, *L;
        if (i < N_W)            { src = W + i;                    H = g_Wh + i;  L = g_Wl + i; }
        else if (i < N_W + N_D) { long o = i - N_W;       src = dec + o; H = g_Dh + o;  L = g_Dl + o; }
        else                    { long o = i - N_W - N_D; src = enc + o; H = g_Enh + o; L = g_Enl + o; }
        float4 x = *reinterpret_cast<const float4*>(src);
        __nv_bfloat16 h0,h1,h2,h3,l0,l1,l2,l3;
        cvt2(x.x,h0,l0); cvt2(x.y,h1,l1); cvt2(x.z,h2,l2); cvt2(x.w,h3,l3);
        reinterpret_cast<__nv_bfloat162*>(H)[0] = __nv_bfloat162(h0,h1);
        reinterpret_cast<__nv_bfloat162*>(H)[1] = __nv_bfloat162(h2,h3);
        reinterpret_cast<__nv_bfloat162*>(L)[0] = __nv_bfloat162(l0,l1);
        reinterpret_cast<__nv_bfloat162*>(L)[1] = __nv_bfloat162(l2,l3);
    } else {
        __shared__ float t[32][33];
        const int eb  = bid - NB_CVT;
        const int b   = eb >> 8;
        const int rem = eb & 255;
        const int j0  = (rem >> 4) * 32;
        const int d0  = (rem & 15) * 32;
        const int tx = tid & 31, ty = tid >> 5;
        const float* e = enc + (long)b * TE * HH;
        #pragma unroll
        for (int p = 0; p < 4; ++p)
            t[ty + p*8][tx] = e[(long)(j0 + ty + p*8) * HH + d0 + tx];
        __syncthreads();
        #pragma unroll
        for (int p = 0; p < 4; ++p) {
            int d = d0 + ty + p*8;
            float x = t[tx][ty + p*8];
            __nv_bfloat16 h, l; cvt2(x, h, l);
            long o = (long)b * HH * TE + (long)d * TE + j0 + tx;
            g_ETh[o] = h; g_ETl[o] = l;
        }
    }
}

// ---------------------------------------------------------------------------
// hi/lo bf16 GEMM body, C = A @ B^T, CTA tile MT x 64, BK=32, 256 threads,
// cp.async double-buffered.
// MT=128: 4x2 warp grid, warp tile 32x32 (12 mma : 8 frag-loads per k2).
// MT=64 : 2x4 warp grid, warp tile 32x16.
// MODE 0: C1 = acc (+bias[col]); Exh/Exl = hilo(exp(C1))
// MODE 1: raw partial -> C1 + kz*partStride (direct wmma gmem store)
// ---------------------------------------------------------------------------
template<int MT, int MODE, int SPLITK>
__device__ __forceinline__ void gemm_body(
    char* dsm,
    const __nv_bfloat16* Ah, const __nv_bfloat16* Al, int lda, long sA,
    const __nv_bfloat16* Bh, const __nv_bfloat16* Bl, int ldb, long sB,
    float* C1, int ldc, long sC, long partStride,
    __nv_bfloat16* Exh, __nv_bfloat16* Exl,
    int K, const float* bias,
    int bx, int by, int bz)
{
    constexpr int BKP = 40;
    constexpr int NJ  = (MT == 128) ? 2 : 1;      // 16-col frags per warp
    __nv_bfloat16* As = reinterpret_cast<__nv_bfloat16*>(dsm);   // [2 stg][2 hl][MT*BKP]
    __nv_bfloat16* Bs = As + 2*2*MT*BKP;                         // [2 stg][2 hl][64*BKP]
    float* Cs = reinterpret_cast<float*>(dsm);

    const int tid = threadIdx.x;
    const int wid = tid >> 5;
    const int wr  = (MT == 128) ? (wid >> 1) : (wid >> 2);
    const int wc  = (MT == 128) ? (wid & 1)  : (wid & 3);
    const int bb = bz / SPLITK, kz = bz % SPLITK;
    const int Ks = K / SPLITK, kbase = kz * Ks, nslab = Ks / 32;

    const __nv_bfloat16* Ah0 = Ah + (long)bb*sA + (long)(by*MT)*lda + kbase;
    const __nv_bfloat16* Al0 = Al + (long)bb*sA + (long)(by*MT)*lda + kbase;
    const __nv_bfloat16* Bh0 = Bh + (long)bb*sB + (long)(bx*64)*ldb + kbase;
    const __nv_bfloat16* Bl0 = Bl + (long)bb*sB + (long)(bx*64)*ldb + kbase;

    const int ar = tid >> 2, ac = (tid & 3) * 8;

    wmma::fragment<wmma::accumulator, 16, 16, 16, float> acc[2][NJ];
    #pragma unroll
    for (int i = 0; i < 2; ++i)
        #pragma unroll
        for (int j = 0; j < NJ; ++j)
            wmma::fill_fragment(acc[i][j], 0.0f);

    #define STAGE(d, k0) do {                                                             \
        _Pragma("unroll")                                                                 \
        for (int p = 0; p < MT/64; ++p) {                                                 \
            int rr = ar + p*64;                                                           \
            cpa16(s2u(As + ((d)*2+0)*MT*BKP + rr*BKP + ac), Ah0 + (long)rr*lda + (k0) + ac); \
            cpa16(s2u(As + ((d)*2+1)*MT*BKP + rr*BKP + ac), Al0 + (long)rr*lda + (k0) + ac); \
        }                                                                                 \
        cpa16(s2u(Bs + ((d)*2+0)*64*BKP + ar*BKP + ac), Bh0 + (long)ar*ldb + (k0) + ac);  \
        cpa16(s2u(Bs + ((d)*2+1)*64*BKP + ar*BKP + ac), Bl0 + (long)ar*ldb + (k0) + ac);  \
    } while (0)

    STAGE(0, 0);
    CP_COMMIT();

    for (int s = 0; s < nslab; ++s) {
        const int d = s & 1;
        if (s + 1 < nslab) {
            STAGE(1 - d, (s + 1) * 32);
            CP_COMMIT();
            CP_WAIT1();
        } else {
            CP_WAIT0();
        }
        __syncthreads();

        const __nv_bfloat16* a_h = As + (d*2+0)*MT*BKP;
        const __nv_bfloat16* a_l = As + (d*2+1)*MT*BKP;
        const __nv_bfloat16* b_h = Bs + (d*2+0)*64*BKP;
        const __nv_bfloat16* b_l = Bs + (d*2+1)*64*BKP;

        #pragma unroll
        for (int k2 = 0; k2 < 32; k2 += 16) {
            wmma::fragment<wmma::matrix_a, 16, 16, 16, __nv_bfloat16, wmma::row_major> fah[2], fal[2];
            wmma::fragment<wmma::matrix_b, 16, 16, 16, __nv_bfloat16, wmma::col_major> fbh[NJ], fbl[NJ];
            #pragma unroll
            for (int i = 0; i < 2; ++i) {
                wmma::load_matrix_sync(fah[i], a_h + (wr*32 + 16*i)*BKP + k2, BKP);
                wmma::load_matrix_sync(fal[i], a_l + (wr*32 + 16*i)*BKP + k2, BKP);
            }
            #pragma unroll
            for (int j = 0; j < NJ; ++j) {
                wmma::load_matrix_sync(fbh[j], b_h + (wc*(16*NJ) + 16*j)*BKP + k2, BKP);
                wmma::load_matrix_sync(fbl[j], b_l + (wc*(16*NJ) + 16*j)*BKP + k2, BKP);
            }
            #pragma unroll
            for (int i = 0; i < 2; ++i)
                #pragma unroll
                for (int j = 0; j < NJ; ++j) {
                    wmma::mma_sync(acc[i][j], fah[i], fbh[j], acc[i][j]);
                    wmma::mma_sync(acc[i][j], fah[i], fbl[j], acc[i][j]);
                    wmma::mma_sync(acc[i][j], fal[i], fbh[j], acc[i][j]);
                }
        }
        __syncthreads();
    }
    #undef STAGE

    const int m0 = by * MT, n0 = bx * 64;

    if (MODE == 1) {
        float* Cp = C1 + (long)kz * partStride + (long)bb * sC;
        #pragma unroll
        for (int i = 0; i < 2; ++i)
            #pragma unroll
            for (int j = 0; j < NJ; ++j)
                wmma::store_matrix_sync(
                    &Cp[(long)(m0 + wr*32 + 16*i) * ldc + n0 + wc*(16*NJ) + 16*j],
                    acc[i][j], ldc, wmma::mem_row_major);
    } else {
        #pragma unroll
        for (int i = 0; i < 2; ++i)
            #pragma unroll
            for (int j = 0; j < NJ; ++j)
                wmma::store_matrix_sync(&Cs[(wr*32 + 16*i)*68 + wc*(16*NJ) + 16*j],
                                        acc[i][j], 68, wmma::mem_row_major);
        __syncthreads();
        #pragma unroll
        for (int q = 0; q < (MT*64)/1024; ++q) {
            int idx = (tid + q*256) * 4;
            int r = idx >> 6, c = idx & 63;
            float4 vv = *reinterpret_cast<float4*>(&Cs[r*68 + c]);
            if (bias) {
                vv.x += bias[n0 + c + 0]; vv.y += bias[n0 + c + 1];
                vv.z += bias[n0 + c + 2]; vv.w += bias[n0 + c + 3];
            }
            long gi = (long)bb*sC + (long)(m0 + r)*ldc + n0 + c;
            *reinterpret_cast<float4*>(&C1[gi]) = vv;
            __nv_bfloat16 h0,h1,h2,h3,l0,l1,l2,l3;
            cvt2(expf(vv.x),h0,l0); cvt2(expf(vv.y),h1,l1);
            cvt2(expf(vv.z),h2,l2); cvt2(expf(vv.w),h3,l3);
            reinterpret_cast<__nv_bfloat162*>(&Exh[gi])[0] = __nv_bfloat162(h0,h1);
            reinterpret_cast<__nv_bfloat162*>(&Exh[gi])[1] = __nv_bfloat162(h2,h3);
            reinterpret_cast<__nv_bfloat162*>(&Exl[gi])[0] = __nv_bfloat162(l0,l1);
            reinterpret_cast<__nv_bfloat162*>(&Exl[gi])[1] = __nv_bfloat162(l2,l3);
        }
    }
}

// Fused GEMM1 (y<4: u = dec@W_dec^T + bias, M=512) + GEMM2 (y>=4: v = enc@W_enc^T,
// M=4096), 128x64 tiles, exp epilogues. grid (8, 36).
__global__ void __launch_bounds__(256, 2) gemm12_k(const float* __restrict__ bias)
{
    extern __shared__ char dsm[];
    if (blockIdx.y < 4)
        gemm_body<128,0,1>(dsm, g_Dh, g_Dl, HH, 0L, g_Wh, g_Wl, 2*HH, 0L,
                           g_u, HH, 0L, 0L, g_Euh, g_Eul, HH, bias,
                           blockIdx.x, blockIdx.y, 0);
    else
        gemm_body<128,0,1>(dsm, g_Enh, g_Enl, HH, 0L, g_Wh + HH, g_Wl + HH, 2*HH, 0L,
                           g_v, HH, 0L, 0L, g_Evh, g_Evl, HH, nullptr,
                           blockIdx.x, blockIdx.y - 4, 0);
}

// ---------------------------------------------------------------------------
// Fused: blocks [0,256) = P[b,i,j] = Eu.Ev split-K=4 raw partials (64x64);
//        blocks [256, 768) = colsum j-split partials.
// ---------------------------------------------------------------------------
__global__ void __launch_bounds__(256) gemm4_colsum_k(
    const float* __restrict__ enc)
{
    extern __shared__ char dsm[];
    const int bid = blockIdx.x;
    if (bid < 256) {
        gemm_body<64,1,4>(dsm, g_Euh, g_Eul, HH, (long)TD*HH, g_Evh, g_Evl, HH, (long)TE*HH,
                          g_pA, TE, (long)TD*TE, (long)BSZ*TD*TE, nullptr, nullptr, HH, nullptr,
                          bid & 7, 0, bid >> 3);
    } else {
        const int cb   = bid - 256;
        const int g    = cb >> 7;
        const int rem  = cb & 127;
        const int b    = rem >> 4;
        const int dblk = rem & 15;
        const int tid  = threadIdx.x;
        const int lane = tid & 31, jg = tid >> 5;
        const int d    = dblk * 32 + lane;
        const float* e  = enc + (long)b * TE * HH + d;
        const float* vv = g_v + (long)b * TE * HH + d;
        float s1 = 0.f, s2 = 0.f;
        const int j0 = g * 128;
        #pragma unroll 8
        for (int j = j0 + jg; j < j0 + 128; j += 8) {
            float ev = e[(long)j * HH];
            s1 += ev;
            s2 += vv[(long)j * HH] * ev;
        }
        float* sh1 = reinterpret_cast<float*>(dsm);
        float* sh2 = sh1 + 256;
        sh1[jg*32 + lane] = s1; sh2[jg*32 + lane] = s2;
        __syncthreads();
        if (jg == 0) {
            float t1 = 0.f, t2 = 0.f;
            #pragma unroll
            for (int q = 0; q < 8; ++q) { t1 += sh1[q*32 + lane]; t2 += sh2[q*32 + lane]; }
            g_cS1[g*BSZ*HH + b*HH + d] = t1;
            g_cS2[g*BSZ*HH + b*HH + d] = t2;
        }
    }
}

// Q[b,i,d] = lse[b,i,:] . encT[b,d,:]  raw partials, split-K=4. grid (8,1,32).
__global__ void __launch_bounds__(256) gemm6_k()
{
    extern __shared__ char dsm[];
    gemm_body<64,1,4>(dsm, g_Lh, g_Ll, TE, (long)TD*TE, g_ETh, g_ETl, TE, (long)HH*TE,
                      g_pA, HH, (long)TD*HH, (long)BSZ*TD*HH, nullptr, nullptr, TE, nullptr,
                      blockIdx.x, 0, blockIdx.z);
}

// lse = log(sum of 4 partials) -> hi/lo bf16
__global__ void __launch_bounds__(128) lse_comb(const float* __restrict__ p)
{
    const long N = (long)BSZ*TD*TE;
    long i = ((long)blockIdx.x * 128 + threadIdx.x) * 4;
    float4 a = *reinterpret_cast<const float4*>(&p[i]);
    float4 b = *reinterpret_cast<const float4*>(&p[i + N]);
    float4 c = *reinterpret_cast<const float4*>(&p[i + 2*N]);
    float4 e = *reinterpret_cast<const float4*>(&p[i + 3*N]);
    __nv_bfloat16 h0,h1,h2,h3,l0,l1,l2,l3;
    cvt2(logf((a.x+b.x)+(c.x+e.x)), h0,l0);
    cvt2(logf((a.y+b.y)+(c.y+e.y)), h1,l1);
    cvt2(logf((a.z+b.z)+(c.z+e.z)), h2,l2);
    cvt2(logf((a.w+b.w)+(c.w+e.w)), h3,l3);
    reinterpret_cast<__nv_bfloat162*>(&g_Lh[i])[0] = __nv_bfloat162(h0,h1);
    reinterpret_cast<__nv_bfloat162*>(&g_Lh[i])[1] = __nv_bfloat162(h2,h3);
    reinterpret_cast<__nv_bfloat162*>(&g_Ll[i])[0] = __nv_bfloat162(l0,l1);
    reinterpret_cast<__nv_bfloat162*>(&g_Ll[i])[1] = __nv_bfloat162(l2,l3);
}

// out = u*(sum cS1) + (sum cS2) - sum of 4 Q partials
__global__ void __launch_bounds__(128) final_comb(
    const float* __restrict__ p, const float* __restrict__ u,
    float* __restrict__ out)
{
    const long N = (long)BSZ*TD*HH;
    long i = ((long)blockIdx.x * 128 + threadIdx.x) * 4;
    int b = (int)(i >> 15);
    int d = (int)(i & (HH - 1));
    float4 a = *reinterpret_cast<const float4*>(&p[i]);
    float4 c = *reinterpret_cast<const float4*>(&p[i + N]);
    float4 e = *reinterpret_cast<const float4*>(&p[i + 2*N]);
    float4 f = *reinterpret_cast<const float4*>(&p[i + 3*N]);
    float4 uu = *reinterpret_cast<const float4*>(&u[i]);
    float4 s1 = make_float4(0.f,0.f,0.f,0.f), s2 = make_float4(0.f,0.f,0.f,0.f);
    #pragma unroll
    for (int g = 0; g < 4; ++g) {
        float4 x1 = *reinterpret_cast<const float4*>(&g_cS1[g*BSZ*HH + b*HH + d]);
        float4 x2 = *reinterpret_cast<const float4*>(&g_cS2[g*BSZ*HH + b*HH + d]);
        s1.x += x1.x; s1.y += x1.y; s1.z += x1.z; s1.w += x1.w;
        s2.x += x2.x; s2.y += x2.y; s2.z += x2.z; s2.w += x2.w;
    }
    float4 o;
    o.x = uu.x*s1.x + s2.x - ((a.x+c.x)+(e.x+f.x));
    o.y = uu.y*s1.y + s2.y - ((a.y+c.y)+(e.y+f.y));
    o.z = uu.z*s1.z + s2.z - ((a.z+c.z)+(e.z+f.z));
    o.w = uu.w*s1.w + s2.w - ((a.w+c.w)+(e.w+f.w));
    *reinterpret_cast<float4*>(&out[i]) = o;
}

// ---------------------------------------------------------------------------
extern "C" void kernel_launch(void* const* d_in, const int* in_sizes, int n_in,
                              void* d_out, int out_size)
{
    const float *enc = nullptr, *dec = nullptr, *W = nullptr, *bias = nullptr;
    for (int i = 0; i < n_in; ++i) {
        switch (in_sizes[i]) {
            case BSZ*TE*HH: enc  = (const float*)d_in[i]; break;
            case BSZ*TD*HH: dec  = (const float*)d_in[i]; break;
            case HH*2*HH:   W    = (const float*)d_in[i]; break;
            case HH:        bias = (const float*)d_in[i]; break;
        }
    }
    float* out = (float*)d_out;

    float *u, *pA;
    cudaGetSymbolAddress((void**)&u,  g_u);
    cudaGetSymbolAddress((void**)&pA, g_pA);

    constexpr int SMB64  = 2*2*(64 + 64)  * 40 * 2;   // 40960
    constexpr int SMB128 = 2*2*(128 + 64) * 40 * 2;   // 61440
    cudaFuncSetAttribute(gemm12_k, cudaFuncAttributeMaxDynamicSharedMemorySize, SMB128);

    // 0) convert W, dec, enc to hi/lo bf16 + build encT (fused)
    prep_k<<<NB_CVT + NB_ET, 256>>>(W, dec, enc);

    // 1+2) fused (128x64 tiles): u = dec@W_dec^T + bias, Eu=exp(u); v = enc@W_enc^T, Ev=exp(v)
    gemm12_k<<<dim3(8, 4 + 32, 1), 256, SMB128>>>(bias);

    // 3+4) fused: P = Eu.Ev partials (split-K=4) + colsum j-split partials
    gemm4_colsum_k<<<256 + 512, 256, SMB64>>>(enc);

    // 5) lse = log(sum partials) -> hi/lo bf16
    lse_comb<<<(BSZ*TD*TE)/512, 128>>>(pA);

    // 6) Q = lse . encT partials (split-K=4)
    gemm6_k<<<dim3(8, 1, BSZ*4), 256, SMB64>>>();

    // 7) out = u*S1 + S2 - sum partials
    final_comb<<<(BSZ*TD*HH)/512, 128>>>(pA, u, out);
}